// round 6
// baseline (speedup 1.0000x reference)
#include <cuda_runtime.h>
#include <cuda_bf16.h>

// ---------------------------------------------------------------------------
// 2-layer GCN:  out = GCNConv(relu(GCNConv(x, W1, b1)), W2, b2)
// N = 50000, E = 800000, 128 -> 128 -> 64
//
// RULES LEARNED:
//  - no __device__ symbol may be referenced from host code (capture breaks)
//  - identify inputs by element count (in_sizes), NOT by position
//  - edge_index dtype is ambiguous (JAX x64-disabled => int32): probe it on
//    device (int64 little-endian has zero high words; int32 doesn't)
//  - bounds-guard every data-derived index
// ---------------------------------------------------------------------------

#define MAX_N 50000
#define MAX_E 800000

__device__ __align__(16) float g_h   [MAX_N * 128]; // layer1 relu out (layer2 input)
__device__ __align__(16) float g_y   [MAX_N * 128]; // gemm output (both layers)
__device__ __align__(16) float g_agg [MAX_N * 128]; // aggregation accumulator
__device__ __align__(16) float g_deg [MAX_N];
__device__ __align__(16) float g_dinv[MAX_N];
__device__ __align__(16) float g_norm[MAX_E];
__device__ __align__(16) int   g_src [MAX_E];
__device__ __align__(16) int   g_dst [MAX_E];
__device__ int g_is64;

// ---------------------------------------------------------------------------
// Structure preprocessing (once; reused by both layers)
// ---------------------------------------------------------------------------

// Probe edge_index dtype. For int64 (values in [0, 2^31)), every odd 32-bit
// word is 0. For int32 node ids, odd words are random ids (almost surely
// nonzero somewhere in 256 words).
__global__ void k_detect_dtype(const int* __restrict__ ei_raw, int n_words) {
    if (threadIdx.x == 0 && blockIdx.x == 0) {
        int is64 = 1;
        for (int i = 1; i < 256 && i < n_words; i += 2)
            if (ei_raw[i] != 0) { is64 = 0; break; }
        g_is64 = is64;
    }
}

__global__ void k_deg_init(int n) {
    int i = blockIdx.x * blockDim.x + threadIdx.x;
    if (i < n) g_deg[i] = 1.0f;                    // self-loop
}

__global__ void k_prep_edges(const void* __restrict__ ei, int E, int n) {
    int e = blockIdx.x * blockDim.x + threadIdx.x;
    if (e >= E) return;
    long long sl, dl;
    if (g_is64) {
        const long long* p = (const long long*)ei;
        sl = p[e];
        dl = p[E + e];
    } else {
        const int* p = (const int*)ei;
        sl = p[e];
        dl = p[E + e];
    }
    int s = ((unsigned long long)sl < (unsigned long long)n) ? (int)sl : 0;
    int d = ((unsigned long long)dl < (unsigned long long)n) ? (int)dl : 0;
    g_src[e] = s;
    g_dst[e] = d;
    atomicAdd(&g_deg[d], 1.0f);
}

__global__ void k_dinv(int n) {
    int i = blockIdx.x * blockDim.x + threadIdx.x;
    if (i < n) g_dinv[i] = rsqrtf(g_deg[i]);
}

__global__ void k_norm(int E) {
    int e = blockIdx.x * blockDim.x + threadIdx.x;
    if (e >= E) return;
    g_norm[e] = g_dinv[g_src[e]] * g_dinv[g_dst[e]];
}

// ---------------------------------------------------------------------------
// GEMM + fused self-loop init.
//   LAYER2==false:  g_y <- X @ W     (X = harness input x)
//   LAYER2==true :  g_y <- g_h @ W
// Epilogue also writes g_agg[node,:] = dinv[node]^2 * y[node,:]
// Block: 32 nodes, dim3(32, 8). Each thread: 4 nodes x VEC cols.
// ---------------------------------------------------------------------------

template <int NOUT, bool LAYER2>
__global__ __launch_bounds__(256)
void k_gemm(const float* __restrict__ Xin, const float* __restrict__ W, int n) {
    constexpr int VEC = NOUT / 32;          // 4 (128) or 2 (64)
    __shared__ float xs[32][128];

    const float* X = LAYER2 ? (const float*)g_h : Xin;

    const int tx = threadIdx.x;             // 0..31 (col group)
    const int ty = threadIdx.y;             // 0..7  (node group of 4)
    const int node0 = blockIdx.x * 32;
    const int tid = ty * 32 + tx;

    const float4* X4 = (const float4*)X;
    float4* xs4 = (float4*)&xs[0][0];
#pragma unroll
    for (int i = 0; i < 4; i++) {
        int idx  = tid + i * 256;
        int row  = idx >> 5;
        int c4   = idx & 31;
        int node = node0 + row;
        float4 v = (node < n) ? X4[(size_t)node * 32 + c4] : make_float4(0.f, 0.f, 0.f, 0.f);
        xs4[row * 32 + c4] = v;
    }
    __syncthreads();

    float acc[4][VEC];
#pragma unroll
    for (int m = 0; m < 4; m++)
#pragma unroll
        for (int v = 0; v < VEC; v++) acc[m][v] = 0.f;

    const int col = tx * VEC;
#pragma unroll 8
    for (int k = 0; k < 128; k++) {
        float wv[VEC];
        if (VEC == 4) {
            float4 w = *(const float4*)&W[k * NOUT + col];
            wv[0] = w.x; wv[1] = w.y; wv[2] = w.z; wv[3] = w.w;
        } else {
            float2 w = *(const float2*)&W[k * NOUT + col];
            wv[0] = w.x; wv[1] = w.y;
        }
#pragma unroll
        for (int m = 0; m < 4; m++) {
            float xv = xs[ty * 4 + m][k];
#pragma unroll
            for (int v = 0; v < VEC; v++) acc[m][v] += xv * wv[v];
        }
    }

#pragma unroll
    for (int m = 0; m < 4; m++) {
        int node = node0 + ty * 4 + m;
        if (node >= n) continue;
        float dv  = g_dinv[node];
        float dv2 = dv * dv;
        if (VEC == 4) {
            float4 o = make_float4(acc[m][0], acc[m][1], acc[m][2], acc[m][3]);
            *(float4*)&g_y[(size_t)node * NOUT + col] = o;
            float4 a = make_float4(dv2 * o.x, dv2 * o.y, dv2 * o.z, dv2 * o.w);
            *(float4*)&g_agg[(size_t)node * NOUT + col] = a;
        } else {
            float2 o = make_float2(acc[m][0], acc[m][1]);
            *(float2*)&g_y[(size_t)node * NOUT + col] = o;
            float2 a = make_float2(dv2 * o.x, dv2 * o.y);
            *(float2*)&g_agg[(size_t)node * NOUT + col] = a;
        }
    }
}

// ---------------------------------------------------------------------------
// Edge scatter:  g_agg[dst,:] += norm[e] * g_y[src,:]    (warp per edge)
// ---------------------------------------------------------------------------

template <int NOUT>
__global__ __launch_bounds__(256)
void k_scatter(int E) {
    constexpr int VEC = NOUT / 32;          // 4 or 2
    int warp = (blockIdx.x * blockDim.x + threadIdx.x) >> 5;
    int lane = threadIdx.x & 31;
    if (warp >= E) return;
    int   s   = g_src[warp];
    int   d   = g_dst[warp];
    float nrm = g_norm[warp];

    if (VEC == 4) {
        float4 hv = *(const float4*)&g_y[(size_t)s * 128 + lane * 4];
        float* a = &g_agg[(size_t)d * 128 + lane * 4];
        atomicAdd(a + 0, nrm * hv.x);
        atomicAdd(a + 1, nrm * hv.y);
        atomicAdd(a + 2, nrm * hv.z);
        atomicAdd(a + 3, nrm * hv.w);
    } else {
        float2 hv = *(const float2*)&g_y[(size_t)s * 64 + lane * 2];
        float* a = &g_agg[(size_t)d * 64 + lane * 2];
        atomicAdd(a + 0, nrm * hv.x);
        atomicAdd(a + 1, nrm * hv.y);
    }
}

// ---------------------------------------------------------------------------
// Epilogues
// ---------------------------------------------------------------------------

__global__ void k_bias_relu(const float* __restrict__ b, int n) {
    int idx = blockIdx.x * blockDim.x + threadIdx.x;
    if (idx >= n * 128) return;
    g_h[idx] = fmaxf(g_agg[idx] + b[idx & 127], 0.f);
}

__global__ void k_bias_out(const float* __restrict__ b, float* __restrict__ out, int n) {
    int idx = blockIdx.x * blockDim.x + threadIdx.x;
    if (idx >= n * 64) return;
    out[idx] = g_agg[idx] + b[idx & 63];
}

// ---------------------------------------------------------------------------
// Launch. Inputs identified by ELEMENT COUNT (robust to metadata order):
//   x:6,400,000  edge_index:1,600,000  W1:16,384  W2:8,192  b1:128  b2:64
// ---------------------------------------------------------------------------

extern "C" void kernel_launch(void* const* d_in, const int* in_sizes, int n_in,
                              void* d_out, int out_size) {
    const float* x  = nullptr;
    const void*  ei = nullptr;
    const float* W1 = nullptr;
    const float* b1 = nullptr;
    const float* W2 = nullptr;
    const float* b2 = nullptr;

    int big0 = -1, big1 = -1;                     // two largest tensors
    for (int i = 0; i < n_in; i++) {
        if (big0 < 0 || in_sizes[i] > in_sizes[big0]) { big1 = big0; big0 = i; }
        else if (big1 < 0 || in_sizes[i] > in_sizes[big1]) { big1 = i; }
    }
    x  = (const float*)d_in[big0];
    ei = (const void*)d_in[big1];
    const int sz_x  = in_sizes[big0];
    const int sz_ei = in_sizes[big1];
    for (int i = 0; i < n_in; i++) {
        if (i == big0 || i == big1) continue;
        switch (in_sizes[i]) {
            case 16384: W1 = (const float*)d_in[i]; break;
            case 8192:  W2 = (const float*)d_in[i]; break;
            case 128:   b1 = (const float*)d_in[i]; break;
            case 64:    b2 = (const float*)d_in[i]; break;
            default: break;
        }
    }

    const int N = sz_x / 128;          // 50000
    const int E = sz_ei / 2;           // 800000
    float* out = (float*)d_out;

    const int TB = 256;
    dim3 gemmBlk(32, 8);
    int gemmGrid = (N + 31) / 32;
    int scatGrid = (int)(((long long)E * 32 + TB - 1) / TB);

    // ---- structure preprocessing ----
    k_detect_dtype<<<1, 32>>>((const int*)ei, 2 * E);
    k_deg_init<<<(N + TB - 1) / TB, TB>>>(N);
    k_prep_edges<<<(E + TB - 1) / TB, TB>>>(ei, E, N);
    k_dinv<<<(N + TB - 1) / TB, TB>>>(N);
    k_norm<<<(E + TB - 1) / TB, TB>>>(E);

    // ---- layer 1 ----
    k_gemm<128, false><<<gemmGrid, gemmBlk>>>(x, W1, N);
    k_scatter<128><<<scatGrid, TB>>>(E);
    k_bias_relu<<<(N * 128 + TB - 1) / TB, TB>>>(b1, N);

    // ---- layer 2 ----
    k_gemm<64, true><<<gemmGrid, gemmBlk>>>(x /*unused*/, W2, N);
    k_scatter<64><<<scatGrid, TB>>>(E);
    k_bias_out<<<(N * 64 + TB - 1) / TB, TB>>>(b2, out, N);
}

// round 8
// speedup vs baseline: 1.6837x; 1.6837x over previous
#include <cuda_runtime.h>
#include <cuda_bf16.h>

// ---------------------------------------------------------------------------
// 2-layer GCN:  out = GCNConv(relu(GCNConv(x, W1, b1)), W2, b2)
// N = 50000, E = 800000, 128 -> 128 -> 64
//
// R8 (= R7 resubmit; container infra failed): CSR-by-dst + register
// accumulating gather (NO float atomics), bias/relu fused into gather.
// RULES LEARNED:
//  - no __device__ symbol referenced from host code
//  - identify inputs by element count; probe edge dtype on device
// ---------------------------------------------------------------------------

#define MAX_N 50000
#define MAX_E 800000

__device__ __align__(16) float     g_h   [MAX_N * 128]; // layer1 output (layer2 input)
__device__ __align__(16) float     g_y   [MAX_N * 128]; // gemm output (both layers)
__device__ __align__(16) float     g_dinv[MAX_N];
__device__ __align__(16) int       g_src [MAX_E];
__device__ __align__(16) int       g_dst [MAX_E];
__device__ __align__(16) long long g_edge[MAX_E];       // packed (norm<<32)|src
__device__ __align__(16) int       g_cnt [MAX_N];
__device__ __align__(16) int       g_row [MAX_N + 1];
__device__ __align__(16) int       g_cur [MAX_N];
__device__ int g_is64;

// ---------------------------------------------------------------------------
// Preprocessing
// ---------------------------------------------------------------------------

__global__ void k_detect_dtype(const int* __restrict__ ei_raw, int n_words) {
    if (threadIdx.x == 0 && blockIdx.x == 0) {
        int is64 = 1;
        for (int i = 1; i < 256 && i < n_words; i += 2)
            if (ei_raw[i] != 0) { is64 = 0; break; }
        g_is64 = is64;
    }
}

__global__ void k_zero(int n) {
    int i = blockIdx.x * blockDim.x + threadIdx.x;
    if (i < n) g_cnt[i] = 0;
}

__global__ void k_edges(const void* __restrict__ ei, int E, int n) {
    int e = blockIdx.x * blockDim.x + threadIdx.x;
    if (e >= E) return;
    long long sl, dl;
    if (g_is64) {
        const long long* p = (const long long*)ei;
        sl = p[e]; dl = p[E + e];
    } else {
        const int* p = (const int*)ei;
        sl = p[e]; dl = p[E + e];
    }
    int s = ((unsigned long long)sl < (unsigned long long)n) ? (int)sl : 0;
    int d = ((unsigned long long)dl < (unsigned long long)n) ? (int)dl : 0;
    g_src[e] = s;
    g_dst[e] = d;
    atomicAdd(&g_cnt[d], 1);
}

__global__ void k_scan(int n, int E) {
    __shared__ int ps[1024];
    const int t = threadIdx.x;
    const int chunk = (n + 1023) / 1024;
    const int lo = t * chunk;
    const int hi = (lo + chunk < n) ? lo + chunk : n;

    int sum = 0;
    for (int i = lo; i < hi; i++) sum += g_cnt[i];
    ps[t] = sum;
    __syncthreads();

    for (int off = 1; off < 1024; off <<= 1) {
        int v = (t >= off) ? ps[t - off] : 0;
        __syncthreads();
        ps[t] += v;
        __syncthreads();
    }

    int run = (t == 0) ? 0 : ps[t - 1];
    for (int i = lo; i < hi; i++) {
        int c = g_cnt[i];
        g_row[i] = run;
        g_cur[i] = run;
        g_dinv[i] = rsqrtf(1.0f + (float)c);   // +1 self-loop
        run += c;
    }
    if (t == 0) g_row[n] = E;
}

__global__ void k_fill(int E) {
    int e = blockIdx.x * blockDim.x + threadIdx.x;
    if (e >= E) return;
    int s = g_src[e];
    int d = g_dst[e];
    float nm = g_dinv[s] * g_dinv[d];
    int pos = atomicAdd(&g_cur[d], 1);
    g_edge[pos] = ((long long)__float_as_int(nm) << 32) | (unsigned)s;
}

// ---------------------------------------------------------------------------
// GEMM:  g_y <- X @ W   (X = input x for layer1, g_h for layer2)
// Block: 32 nodes, dim3(32,8). Each thread: 4 nodes x VEC cols.
// ---------------------------------------------------------------------------

template <int NOUT, bool LAYER2>
__global__ __launch_bounds__(256)
void k_gemm(const float* __restrict__ Xin, const float* __restrict__ W, int n) {
    constexpr int VEC = NOUT / 32;
    __shared__ float xs[32][128];

    const float* X = LAYER2 ? (const float*)g_h : Xin;

    const int tx = threadIdx.x;
    const int ty = threadIdx.y;
    const int node0 = blockIdx.x * 32;
    const int tid = ty * 32 + tx;

    const float4* X4 = (const float4*)X;
    float4* xs4 = (float4*)&xs[0][0];
#pragma unroll
    for (int i = 0; i < 4; i++) {
        int idx  = tid + i * 256;
        int row  = idx >> 5;
        int c4   = idx & 31;
        int node = node0 + row;
        float4 v = (node < n) ? X4[(size_t)node * 32 + c4] : make_float4(0.f, 0.f, 0.f, 0.f);
        xs4[row * 32 + c4] = v;
    }
    __syncthreads();

    float acc[4][VEC];
#pragma unroll
    for (int m = 0; m < 4; m++)
#pragma unroll
        for (int v = 0; v < VEC; v++) acc[m][v] = 0.f;

    const int col = tx * VEC;
#pragma unroll 8
    for (int k = 0; k < 128; k++) {
        float wv[VEC];
        if (VEC == 4) {
            float4 w = *(const float4*)&W[k * NOUT + col];
            wv[0] = w.x; wv[1] = w.y; wv[2] = w.z; wv[3] = w.w;
        } else {
            float2 w = *(const float2*)&W[k * NOUT + col];
            wv[0] = w.x; wv[1] = w.y;
        }
#pragma unroll
        for (int m = 0; m < 4; m++) {
            float xv = xs[ty * 4 + m][k];
#pragma unroll
            for (int v = 0; v < VEC; v++) acc[m][v] += xv * wv[v];
        }
    }

#pragma unroll
    for (int m = 0; m < 4; m++) {
        int node = node0 + ty * 4 + m;
        if (node >= n) continue;
        if (VEC == 4) {
            *(float4*)&g_y[(size_t)node * NOUT + col] =
                make_float4(acc[m][0], acc[m][1], acc[m][2], acc[m][3]);
        } else {
            *(float2*)&g_y[(size_t)node * NOUT + col] =
                make_float2(acc[m][0], acc[m][1]);
        }
    }
}

// ---------------------------------------------------------------------------
// Gather: acc = dinv[d]^2*y[d,:] + sum_e norm*y[src,:]; fused bias(+relu).
// LAYER1: writes relu(acc+b) to g_h.   else: writes acc+b to dstbuf (d_out).
// NOUT=128: warp per node. NOUT=64: half-warp per node.
// ---------------------------------------------------------------------------

template <int NOUT, bool LAYER1>
__global__ __launch_bounds__(256)
void k_gather(const float* __restrict__ b, float* __restrict__ dstbuf, int n) {
    constexpr int LPN = NOUT / 4;
    constexpr int NPW = 32 / LPN;
    const int warp = (blockIdx.x * blockDim.x + threadIdx.x) >> 5;
    const int lane = threadIdx.x & 31;
    const int sub  = lane / LPN;
    const int l4   = lane % LPN;
    const int d = warp * NPW + sub;
    if (d >= n) return;

    const float4* Y4 = (const float4*)g_y;
    const int begin = g_row[d];
    const int end   = g_row[d + 1];

    float dv  = g_dinv[d];
    float dv2 = dv * dv;
    float4 sv = Y4[(size_t)d * LPN + l4];
    float4 acc = make_float4(dv2 * sv.x, dv2 * sv.y, dv2 * sv.z, dv2 * sv.w);

    int i = begin;
    for (; i + 4 <= end; i += 4) {
        long long p0 = g_edge[i];
        long long p1 = g_edge[i + 1];
        long long p2 = g_edge[i + 2];
        long long p3 = g_edge[i + 3];
        int s0 = (int)(unsigned)p0; float n0 = __int_as_float((int)(p0 >> 32));
        int s1 = (int)(unsigned)p1; float n1 = __int_as_float((int)(p1 >> 32));
        int s2 = (int)(unsigned)p2; float n2 = __int_as_float((int)(p2 >> 32));
        int s3 = (int)(unsigned)p3; float n3 = __int_as_float((int)(p3 >> 32));
        float4 v0 = Y4[(size_t)s0 * LPN + l4];
        float4 v1 = Y4[(size_t)s1 * LPN + l4];
        float4 v2 = Y4[(size_t)s2 * LPN + l4];
        float4 v3 = Y4[(size_t)s3 * LPN + l4];
        acc.x += n0 * v0.x; acc.y += n0 * v0.y; acc.z += n0 * v0.z; acc.w += n0 * v0.w;
        acc.x += n1 * v1.x; acc.y += n1 * v1.y; acc.z += n1 * v1.z; acc.w += n1 * v1.w;
        acc.x += n2 * v2.x; acc.y += n2 * v2.y; acc.z += n2 * v2.z; acc.w += n2 * v2.w;
        acc.x += n3 * v3.x; acc.y += n3 * v3.y; acc.z += n3 * v3.z; acc.w += n3 * v3.w;
    }
    for (; i < end; i++) {
        long long p = g_edge[i];
        int s = (int)(unsigned)p;
        float nm = __int_as_float((int)(p >> 32));
        float4 v = Y4[(size_t)s * LPN + l4];
        acc.x += nm * v.x; acc.y += nm * v.y; acc.z += nm * v.z; acc.w += nm * v.w;
    }

    float4 bb = ((const float4*)b)[l4];
    acc.x += bb.x; acc.y += bb.y; acc.z += bb.z; acc.w += bb.w;
    if (LAYER1) {
        acc.x = fmaxf(acc.x, 0.f); acc.y = fmaxf(acc.y, 0.f);
        acc.z = fmaxf(acc.z, 0.f); acc.w = fmaxf(acc.w, 0.f);
        ((float4*)g_h)[(size_t)d * LPN + l4] = acc;
    } else {
        ((float4*)dstbuf)[(size_t)d * LPN + l4] = acc;
    }
}

// ---------------------------------------------------------------------------
// Launch. Inputs identified by ELEMENT COUNT:
//   x:6,400,000  edge_index:1,600,000  W1:16,384  W2:8,192  b1:128  b2:64
// ---------------------------------------------------------------------------

extern "C" void kernel_launch(void* const* d_in, const int* in_sizes, int n_in,
                              void* d_out, int out_size) {
    const float* x  = nullptr;
    const void*  ei = nullptr;
    const float* W1 = nullptr;
    const float* b1 = nullptr;
    const float* W2 = nullptr;
    const float* b2 = nullptr;

    int big0 = -1, big1 = -1;
    for (int i = 0; i < n_in; i++) {
        if (big0 < 0 || in_sizes[i] > in_sizes[big0]) { big1 = big0; big0 = i; }
        else if (big1 < 0 || in_sizes[i] > in_sizes[big1]) { big1 = i; }
    }
    x  = (const float*)d_in[big0];
    ei = (const void*)d_in[big1];
    const int sz_x  = in_sizes[big0];
    const int sz_ei = in_sizes[big1];
    for (int i = 0; i < n_in; i++) {
        if (i == big0 || i == big1) continue;
        switch (in_sizes[i]) {
            case 16384: W1 = (const float*)d_in[i]; break;
            case 8192:  W2 = (const float*)d_in[i]; break;
            case 128:   b1 = (const float*)d_in[i]; break;
            case 64:    b2 = (const float*)d_in[i]; break;
            default: break;
        }
    }

    const int N = sz_x / 128;          // 50000
    const int E = sz_ei / 2;           // 800000
    float* out = (float*)d_out;

    const int TB = 256;
    dim3 gemmBlk(32, 8);
    int gemmGrid = (N + 31) / 32;

    // ---- CSR build ----
    k_detect_dtype<<<1, 32>>>((const int*)ei, 2 * E);
    k_zero<<<(N + TB - 1) / TB, TB>>>(N);
    k_edges<<<(E + TB - 1) / TB, TB>>>(ei, E, N);
    k_scan<<<1, 1024>>>(N, E);
    k_fill<<<(E + TB - 1) / TB, TB>>>(E);

    // ---- layer 1 ----
    k_gemm<128, false><<<gemmGrid, gemmBlk>>>(x, W1, N);
    k_gather<128, true><<<(N * 32 + TB - 1) / TB, TB>>>(b1, nullptr, N);

    // ---- layer 2 ----
    k_gemm<64, true><<<gemmGrid, gemmBlk>>>(x /*unused*/, W2, N);
    k_gather<64, false><<<(((N + 1) / 2) * 32 + TB - 1) / TB, TB>>>(b2, out, N);
}

// round 9
// speedup vs baseline: 2.6100x; 1.5501x over previous
#include <cuda_runtime.h>
#include <cuda_bf16.h>

// ---------------------------------------------------------------------------
// 2-layer GCN:  out = GCNConv(relu(GCNConv(x, W1, b1)), W2, b2)
// N = 50000, E = 800000, 128 -> 128 -> 64
//
// R9: parallelized CSR row-offset scan (was 109us on ONE block = 39% of
// runtime) into 3 multi-block phases; warp-parallel dtype probe.
// ---------------------------------------------------------------------------

#define MAX_N 50000
#define MAX_E 800000

#define SCAN_B 64
#define SCAN_T 256
// chunk per thread
#define SCAN_C ((MAX_N + SCAN_B * SCAN_T - 1) / (SCAN_B * SCAN_T))   // 4

__device__ __align__(16) float     g_h   [MAX_N * 128]; // layer1 output (layer2 input)
__device__ __align__(16) float     g_y   [MAX_N * 128]; // gemm output (both layers)
__device__ __align__(16) float     g_dinv[MAX_N];
__device__ __align__(16) int       g_src [MAX_E];
__device__ __align__(16) int       g_dst [MAX_E];
__device__ __align__(16) long long g_edge[MAX_E];       // packed (norm<<32)|src
__device__ __align__(16) int       g_cnt [MAX_N];
__device__ __align__(16) int       g_row [MAX_N + 1];
__device__ __align__(16) int       g_cur [MAX_N];
__device__ __align__(16) int       g_part[SCAN_B];      // per-block sums
__device__ __align__(16) int       g_poff[SCAN_B];      // exclusive offsets
__device__ int g_is64;

// ---------------------------------------------------------------------------
// Preprocessing
// ---------------------------------------------------------------------------

// Warp-parallel dtype probe: int64 edge indices (<2^31) have all-zero odd
// 32-bit words; int32 node ids do not.
__global__ void k_detect_dtype(const int* __restrict__ ei_raw, int n_words) {
    int lane = threadIdx.x;                 // 32 threads
    int nonzero = 0;
    for (int i = 1 + 2 * lane; i < 512 && i < n_words; i += 64)
        nonzero |= (ei_raw[i] != 0);
    unsigned m = __ballot_sync(0xFFFFFFFFu, nonzero);
    if (lane == 0) g_is64 = (m == 0);
}

__global__ void k_zero(int n) {
    int i = blockIdx.x * blockDim.x + threadIdx.x;
    if (i < n) g_cnt[i] = 0;
}

__global__ void k_edges(const void* __restrict__ ei, int E, int n) {
    int e = blockIdx.x * blockDim.x + threadIdx.x;
    if (e >= E) return;
    long long sl, dl;
    if (g_is64) {
        const long long* p = (const long long*)ei;
        sl = p[e]; dl = p[E + e];
    } else {
        const int* p = (const int*)ei;
        sl = p[e]; dl = p[E + e];
    }
    int s = ((unsigned long long)sl < (unsigned long long)n) ? (int)sl : 0;
    int d = ((unsigned long long)dl < (unsigned long long)n) ? (int)dl : 0;
    g_src[e] = s;
    g_dst[e] = d;
    atomicAdd(&g_cnt[d], 1);
}

// ---- scan phase A: per-block partial sums over chunks of counts ----
__global__ void k_partsum(int n) {
    __shared__ int sh[SCAN_T];
    const int t = threadIdx.x;
    const int gchunk = blockIdx.x * SCAN_T + t;
    const int lo = gchunk * SCAN_C;
    int sum = 0;
#pragma unroll
    for (int j = 0; j < SCAN_C; j++) {
        int i = lo + j;
        if (i < n) sum += g_cnt[i];
    }
    sh[t] = sum;
    __syncthreads();
    for (int off = SCAN_T / 2; off > 0; off >>= 1) {
        if (t < off) sh[t] += sh[t + off];
        __syncthreads();
    }
    if (t == 0) g_part[blockIdx.x] = sh[0];
}

// ---- scan phase B: exclusive scan of the 64 block sums (one tiny block) ----
__global__ void k_partscan() {
    __shared__ int sh[SCAN_B];
    const int t = threadIdx.x;                 // SCAN_B threads
    sh[t] = g_part[t];
    __syncthreads();
    // inclusive Hillis-Steele
    for (int off = 1; off < SCAN_B; off <<= 1) {
        int v = (t >= off) ? sh[t - off] : 0;
        __syncthreads();
        sh[t] += v;
        __syncthreads();
    }
    g_poff[t] = (t == 0) ? 0 : sh[t - 1];
}

// ---- scan phase C: per-block rescan, write row offsets / cursors / dinv ----
__global__ void k_rowfill(int n, int E) {
    __shared__ int sh[SCAN_T];
    const int t = threadIdx.x;
    const int gchunk = blockIdx.x * SCAN_T + t;
    const int lo = gchunk * SCAN_C;

    int csum[SCAN_C];
    int sum = 0;
#pragma unroll
    for (int j = 0; j < SCAN_C; j++) {
        int i = lo + j;
        int c = (i < n) ? g_cnt[i] : 0;
        csum[j] = c;
        sum += c;
    }
    sh[t] = sum;
    __syncthreads();
    // inclusive scan of thread sums
    for (int off = 1; off < SCAN_T; off <<= 1) {
        int v = (t >= off) ? sh[t - off] : 0;
        __syncthreads();
        sh[t] += v;
        __syncthreads();
    }
    int run = g_poff[blockIdx.x] + ((t == 0) ? 0 : sh[t - 1]);
#pragma unroll
    for (int j = 0; j < SCAN_C; j++) {
        int i = lo + j;
        if (i < n) {
            g_row[i] = run;
            g_cur[i] = run;
            g_dinv[i] = rsqrtf(1.0f + (float)csum[j]);   // +1 self-loop
            run += csum[j];
        }
    }
    if (blockIdx.x == 0 && t == 0) g_row[n] = E;
}

__global__ void k_fill(int E) {
    int e = blockIdx.x * blockDim.x + threadIdx.x;
    if (e >= E) return;
    int s = g_src[e];
    int d = g_dst[e];
    float nm = g_dinv[s] * g_dinv[d];
    int pos = atomicAdd(&g_cur[d], 1);
    g_edge[pos] = ((long long)__float_as_int(nm) << 32) | (unsigned)s;
}

// ---------------------------------------------------------------------------
// GEMM:  g_y <- X @ W   (X = input x for layer1, g_h for layer2)
// Block: 32 nodes, dim3(32,8). Each thread: 4 nodes x VEC cols.
// ---------------------------------------------------------------------------

template <int NOUT, bool LAYER2>
__global__ __launch_bounds__(256)
void k_gemm(const float* __restrict__ Xin, const float* __restrict__ W, int n) {
    constexpr int VEC = NOUT / 32;
    __shared__ float xs[32][128];

    const float* X = LAYER2 ? (const float*)g_h : Xin;

    const int tx = threadIdx.x;
    const int ty = threadIdx.y;
    const int node0 = blockIdx.x * 32;
    const int tid = ty * 32 + tx;

    const float4* X4 = (const float4*)X;
    float4* xs4 = (float4*)&xs[0][0];
#pragma unroll
    for (int i = 0; i < 4; i++) {
        int idx  = tid + i * 256;
        int row  = idx >> 5;
        int c4   = idx & 31;
        int node = node0 + row;
        float4 v = (node < n) ? X4[(size_t)node * 32 + c4] : make_float4(0.f, 0.f, 0.f, 0.f);
        xs4[row * 32 + c4] = v;
    }
    __syncthreads();

    float acc[4][VEC];
#pragma unroll
    for (int m = 0; m < 4; m++)
#pragma unroll
        for (int v = 0; v < VEC; v++) acc[m][v] = 0.f;

    const int col = tx * VEC;
#pragma unroll 8
    for (int k = 0; k < 128; k++) {
        float wv[VEC];
        if (VEC == 4) {
            float4 w = *(const float4*)&W[k * NOUT + col];
            wv[0] = w.x; wv[1] = w.y; wv[2] = w.z; wv[3] = w.w;
        } else {
            float2 w = *(const float2*)&W[k * NOUT + col];
            wv[0] = w.x; wv[1] = w.y;
        }
#pragma unroll
        for (int m = 0; m < 4; m++) {
            float xv = xs[ty * 4 + m][k];
#pragma unroll
            for (int v = 0; v < VEC; v++) acc[m][v] += xv * wv[v];
        }
    }

#pragma unroll
    for (int m = 0; m < 4; m++) {
        int node = node0 + ty * 4 + m;
        if (node >= n) continue;
        if (VEC == 4) {
            *(float4*)&g_y[(size_t)node * NOUT + col] =
                make_float4(acc[m][0], acc[m][1], acc[m][2], acc[m][3]);
        } else {
            *(float2*)&g_y[(size_t)node * NOUT + col] =
                make_float2(acc[m][0], acc[m][1]);
        }
    }
}

// ---------------------------------------------------------------------------
// Gather: acc = dinv[d]^2*y[d,:] + sum_e norm*y[src,:]; fused bias(+relu).
// LAYER1: writes relu(acc+b) to g_h.   else: writes acc+b to dstbuf (d_out).
// NOUT=128: warp per node. NOUT=64: half-warp per node.
// ---------------------------------------------------------------------------

template <int NOUT, bool LAYER1>
__global__ __launch_bounds__(256)
void k_gather(const float* __restrict__ b, float* __restrict__ dstbuf, int n) {
    constexpr int LPN = NOUT / 4;
    constexpr int NPW = 32 / LPN;
    const int warp = (blockIdx.x * blockDim.x + threadIdx.x) >> 5;
    const int lane = threadIdx.x & 31;
    const int sub  = lane / LPN;
    const int l4   = lane % LPN;
    const int d = warp * NPW + sub;
    if (d >= n) return;

    const float4* Y4 = (const float4*)g_y;
    const int begin = g_row[d];
    const int end   = g_row[d + 1];

    float dv  = g_dinv[d];
    float dv2 = dv * dv;
    float4 sv = Y4[(size_t)d * LPN + l4];
    float4 acc = make_float4(dv2 * sv.x, dv2 * sv.y, dv2 * sv.z, dv2 * sv.w);

    int i = begin;
    for (; i + 4 <= end; i += 4) {
        long long p0 = g_edge[i];
        long long p1 = g_edge[i + 1];
        long long p2 = g_edge[i + 2];
        long long p3 = g_edge[i + 3];
        int s0 = (int)(unsigned)p0; float n0 = __int_as_float((int)(p0 >> 32));
        int s1 = (int)(unsigned)p1; float n1 = __int_as_float((int)(p1 >> 32));
        int s2 = (int)(unsigned)p2; float n2 = __int_as_float((int)(p2 >> 32));
        int s3 = (int)(unsigned)p3; float n3 = __int_as_float((int)(p3 >> 32));
        float4 v0 = Y4[(size_t)s0 * LPN + l4];
        float4 v1 = Y4[(size_t)s1 * LPN + l4];
        float4 v2 = Y4[(size_t)s2 * LPN + l4];
        float4 v3 = Y4[(size_t)s3 * LPN + l4];
        acc.x += n0 * v0.x; acc.y += n0 * v0.y; acc.z += n0 * v0.z; acc.w += n0 * v0.w;
        acc.x += n1 * v1.x; acc.y += n1 * v1.y; acc.z += n1 * v1.z; acc.w += n1 * v1.w;
        acc.x += n2 * v2.x; acc.y += n2 * v2.y; acc.z += n2 * v2.z; acc.w += n2 * v2.w;
        acc.x += n3 * v3.x; acc.y += n3 * v3.y; acc.z += n3 * v3.z; acc.w += n3 * v3.w;
    }
    for (; i < end; i++) {
        long long p = g_edge[i];
        int s = (int)(unsigned)p;
        float nm = __int_as_float((int)(p >> 32));
        float4 v = Y4[(size_t)s * LPN + l4];
        acc.x += nm * v.x; acc.y += nm * v.y; acc.z += nm * v.z; acc.w += nm * v.w;
    }

    float4 bb = ((const float4*)b)[l4];
    acc.x += bb.x; acc.y += bb.y; acc.z += bb.z; acc.w += bb.w;
    if (LAYER1) {
        acc.x = fmaxf(acc.x, 0.f); acc.y = fmaxf(acc.y, 0.f);
        acc.z = fmaxf(acc.z, 0.f); acc.w = fmaxf(acc.w, 0.f);
        ((float4*)g_h)[(size_t)d * LPN + l4] = acc;
    } else {
        ((float4*)dstbuf)[(size_t)d * LPN + l4] = acc;
    }
}

// ---------------------------------------------------------------------------
// Launch. Inputs identified by ELEMENT COUNT:
//   x:6,400,000  edge_index:1,600,000  W1:16,384  W2:8,192  b1:128  b2:64
// ---------------------------------------------------------------------------

extern "C" void kernel_launch(void* const* d_in, const int* in_sizes, int n_in,
                              void* d_out, int out_size) {
    const float* x  = nullptr;
    const void*  ei = nullptr;
    const float* W1 = nullptr;
    const float* b1 = nullptr;
    const float* W2 = nullptr;
    const float* b2 = nullptr;

    int big0 = -1, big1 = -1;
    for (int i = 0; i < n_in; i++) {
        if (big0 < 0 || in_sizes[i] > in_sizes[big0]) { big1 = big0; big0 = i; }
        else if (big1 < 0 || in_sizes[i] > in_sizes[big1]) { big1 = i; }
    }
    x  = (const float*)d_in[big0];
    ei = (const void*)d_in[big1];
    const int sz_x  = in_sizes[big0];
    const int sz_ei = in_sizes[big1];
    for (int i = 0; i < n_in; i++) {
        if (i == big0 || i == big1) continue;
        switch (in_sizes[i]) {
            case 16384: W1 = (const float*)d_in[i]; break;
            case 8192:  W2 = (const float*)d_in[i]; break;
            case 128:   b1 = (const float*)d_in[i]; break;
            case 64:    b2 = (const float*)d_in[i]; break;
            default: break;
        }
    }

    const int N = sz_x / 128;          // 50000
    const int E = sz_ei / 2;           // 800000
    float* out = (float*)d_out;

    const int TB = 256;
    dim3 gemmBlk(32, 8);
    int gemmGrid = (N + 31) / 32;

    // ---- CSR build ----
    k_detect_dtype<<<1, 32>>>((const int*)ei, 2 * E);
    k_zero<<<(N + TB - 1) / TB, TB>>>(N);
    k_edges<<<(E + TB - 1) / TB, TB>>>(ei, E, N);
    k_partsum<<<SCAN_B, SCAN_T>>>(N);
    k_partscan<<<1, SCAN_B>>>();
    k_rowfill<<<SCAN_B, SCAN_T>>>(N, E);
    k_fill<<<(E + TB - 1) / TB, TB>>>(E);

    // ---- layer 1 ----
    k_gemm<128, false><<<gemmGrid, gemmBlk>>>(x, W1, N);
    k_gather<128, true><<<(N * 32 + TB - 1) / TB, TB>>>(b1, nullptr, N);

    // ---- layer 2 ----
    k_gemm<64, true><<<gemmGrid, gemmBlk>>>(x /*unused*/, W2, N);
    k_gather<64, false><<<(((N + 1) / 2) * 32 + TB - 1) / TB, TB>>>(b2, out, N);
}